// round 1
// baseline (speedup 1.0000x reference)
#include <cuda_runtime.h>
#include <math.h>

// Problem dims (fixed)
#define BB 2
#define SS 4096
#define DD 512

// Scratch (device globals: allocation-free rule)
__device__ float g_q[(size_t)BB * SS * DD];
__device__ float g_k[(size_t)BB * SS * DD];
__device__ float g_v[(size_t)BB * SS * DD];
__device__ float g_s[(size_t)BB * SS * SS];

// ---------------------------------------------------------------------------
// Tiled fp32 GEMM: C = alpha * A * op(B)
//   TB=false: B is [K,N] row-major (NN)
//   TB=true : B is [N,K] row-major (NT, dot along K)
// Tiles: BM=BN=64, BK=16; 256 threads; each thread 4x4 outputs.
// All dims assumed multiples of tile sizes (true for this problem).
// ---------------------------------------------------------------------------
#define BM 64
#define BN 64
#define BK 16
#define PAD 4  // pad smem rows to keep 16B alignment + reduce conflicts

template <bool TB>
__global__ void __launch_bounds__(256)
gemm_kernel(const float* __restrict__ A, const float* __restrict__ B,
            float* __restrict__ C,
            int M, int N, int K, int lda, int ldb, int ldc,
            long long sA, long long sB, long long sC, float alpha)
{
    __shared__ float As[BK][BM + PAD];
    __shared__ float Bs[BK][BN + PAD];

    const int z = blockIdx.z;
    A += (long long)z * sA;
    B += (long long)z * sB;
    C += (long long)z * sC;

    const int tid = threadIdx.x;
    const int tx = tid & 15;       // 0..15 -> output col group
    const int ty = tid >> 4;       // 0..15 -> output row group
    const int row0 = blockIdx.y * BM;
    const int col0 = blockIdx.x * BN;

    // A-tile (and NT B-tile) loader coords: one float4 per thread
    const int ar  = tid >> 2;        // 0..63
    const int ac4 = (tid & 3) * 4;   // 0,4,8,12
    // NN B-tile loader coords
    const int bk  = tid >> 4;        // 0..15
    const int bn4 = (tid & 15) * 4;  // 0..60

    float acc[4][4] = {};

    for (int k0 = 0; k0 < K; k0 += BK) {
        // Load A tile [BM x BK], store transposed -> As[k][m]
        float4 av = *(const float4*)&A[(long long)(row0 + ar) * lda + k0 + ac4];
        As[ac4 + 0][ar] = av.x;
        As[ac4 + 1][ar] = av.y;
        As[ac4 + 2][ar] = av.z;
        As[ac4 + 3][ar] = av.w;

        if (TB) {
            // B is [N,K]; tile rows are n, cols are k -> store transposed Bs[k][n]
            float4 bv = *(const float4*)&B[(long long)(col0 + ar) * ldb + k0 + ac4];
            Bs[ac4 + 0][ar] = bv.x;
            Bs[ac4 + 1][ar] = bv.y;
            Bs[ac4 + 2][ar] = bv.z;
            Bs[ac4 + 3][ar] = bv.w;
        } else {
            // B is [K,N]; contiguous along n
            float4 bv = *(const float4*)&B[(long long)(k0 + bk) * ldb + col0 + bn4];
            *(float4*)&Bs[bk][bn4] = bv;
        }
        __syncthreads();

#pragma unroll
        for (int kk = 0; kk < BK; kk++) {
            float a[4], b[4];
            *(float4*)a = *(const float4*)&As[kk][ty * 4];
            *(float4*)b = *(const float4*)&Bs[kk][tx * 4];
#pragma unroll
            for (int i = 0; i < 4; i++)
#pragma unroll
                for (int j = 0; j < 4; j++)
                    acc[i][j] += a[i] * b[j];
        }
        __syncthreads();
    }

#pragma unroll
    for (int i = 0; i < 4; i++) {
        float4 v;
        v.x = acc[i][0] * alpha;
        v.y = acc[i][1] * alpha;
        v.z = acc[i][2] * alpha;
        v.w = acc[i][3] * alpha;
        *(float4*)&C[(long long)(row0 + ty * 4 + i) * ldc + col0 + tx * 4] = v;
    }
}

// ---------------------------------------------------------------------------
// Row softmax over n=4096 (one block of 256 threads per row; 16 values/thread)
// ---------------------------------------------------------------------------
__global__ void __launch_bounds__(256)
softmax_kernel(float* __restrict__ s)
{
    __shared__ float red[256];
    const long long row = blockIdx.x;
    float* p = s + row * (long long)SS;
    const int tid = threadIdx.x;

    float v[16];
    float mx = -1e30f;
#pragma unroll
    for (int i = 0; i < 16; i++) {
        v[i] = p[tid + i * 256];
        mx = fmaxf(mx, v[i]);
    }
    red[tid] = mx;
    __syncthreads();
    for (int w = 128; w > 0; w >>= 1) {
        if (tid < w) red[tid] = fmaxf(red[tid], red[tid + w]);
        __syncthreads();
    }
    mx = red[0];
    __syncthreads();

    float sum = 0.0f;
#pragma unroll
    for (int i = 0; i < 16; i++) {
        v[i] = __expf(v[i] - mx);
        sum += v[i];
    }
    red[tid] = sum;
    __syncthreads();
    for (int w = 128; w > 0; w >>= 1) {
        if (tid < w) red[tid] += red[tid + w];
        __syncthreads();
    }
    const float inv = 1.0f / red[0];
#pragma unroll
    for (int i = 0; i < 16; i++)
        p[tid + i * 256] = v[i] * inv;
}

// ---------------------------------------------------------------------------
extern "C" void kernel_launch(void* const* d_in, const int* in_sizes, int n_in,
                              void* d_out, int out_size)
{
    const float* x  = (const float*)d_in[0];
    const float* wq = (const float*)d_in[1];
    const float* wk = (const float*)d_in[2];
    const float* wv = (const float*)d_in[3];
    float* out = (float*)d_out;

    float *q, *k, *v, *s;
    cudaGetSymbolAddress((void**)&q, g_q);
    cudaGetSymbolAddress((void**)&k, g_k);
    cudaGetSymbolAddress((void**)&v, g_v);
    cudaGetSymbolAddress((void**)&s, g_s);

    const long long qkvStride = (long long)SS * DD;       // per-batch Q/K/V
    const long long sStride   = (long long)SS * SS;       // per-batch scores
    const float scale = 1.0f / sqrtf((float)DD);

    dim3 blk(256);

    // 1) QKV projections: [8192,512] x [512,512] (NN)
    {
        dim3 grid(DD / BN, (BB * SS) / BM, 1);
        gemm_kernel<false><<<grid, blk>>>(x, wq, q, BB * SS, DD, DD, DD, DD, DD,
                                          0, 0, 0, 1.0f);
        gemm_kernel<false><<<grid, blk>>>(x, wk, k, BB * SS, DD, DD, DD, DD, DD,
                                          0, 0, 0, 1.0f);
        gemm_kernel<false><<<grid, blk>>>(x, wv, v, BB * SS, DD, DD, DD, DD, DD,
                                          0, 0, 0, 1.0f);
    }

    // 2) scores = scale * Q @ K^T  (NT), per batch
    {
        dim3 grid(SS / BN, SS / BM, BB);
        gemm_kernel<true><<<grid, blk>>>(q, k, s, SS, SS, DD, DD, DD, SS,
                                         qkvStride, qkvStride, sStride, scale);
    }

    // 3) softmax rows
    {
        dim3 grid(BB * SS);
        softmax_kernel<<<grid, blk>>>(s);
    }

    // 4) context = P @ V  (NN), per batch
    {
        dim3 grid(DD / BN, SS / BM, BB);
        gemm_kernel<false><<<grid, blk>>>(s, v, out, SS, DD, SS, SS, DD, DD,
                                          sStride, qkvStride, qkvStride, 1.0f);
    }
}

// round 2
// speedup vs baseline: 3.0342x; 3.0342x over previous
#include <cuda_runtime.h>
#include <math.h>
#include <stdint.h>

// Problem dims (fixed)
#define BB 2
#define SS 4096
#define DD 512

// Scratch (device globals: allocation-free rule)
__device__ float g_q[(size_t)BB * SS * DD];
__device__ float g_k[(size_t)BB * SS * DD];
__device__ float g_v[(size_t)BB * SS * DD];
__device__ float g_s[(size_t)BB * SS * SS];

// ---------------------------------------------------------------------------
// TF32 tensor-core GEMM: C = alpha * A * op(B)
//   TB=false: B is [K,N] row-major (NN)
//   TB=true : B is [N,K] row-major (NT, dot along K)
// CTA tile 128x128x32, 256 threads (8 warps as 2x4), warp tile 64x32,
// mma.sync.aligned.m16n8k8.row.col.f32.tf32.tf32.f32.
// All dims assumed multiples of tile sizes (true for this problem).
// ---------------------------------------------------------------------------
#define BM 128
#define BN 128
#define BK 32

__device__ __forceinline__ uint32_t f2tf32(float f) {
    uint32_t r;
    asm("cvt.rna.tf32.f32 %0, %1;" : "=r"(r) : "f"(f));
    return r;
}

// Swizzled word index for a [row][32-k-words] tile (128B rows, XOR swizzle):
// chunk-of-4-words index ^= (row & 7). Conflict-free for both the float4
// tile stores (one row per 8-lane phase) and the mma fragment loads.
__device__ __forceinline__ int swz(int row, int kw) {
    return row * 32 + (((((kw) >> 2) ^ (row & 7)) << 2) | (kw & 3));
}

template <bool TB>
__global__ void __launch_bounds__(256, 2)
gemm_tf32(const float* __restrict__ A, const float* __restrict__ B,
          float* __restrict__ C, int K, int lda, int ldb, int ldc,
          long long sA, long long sB, long long sC, float alpha)
{
    // A always [m][k]-major swizzled. B: TB -> [n][k]-major swizzled,
    // NN -> [k][n] with +8 pad.
    __shared__ uint32_t As[BM * BK];
    __shared__ uint32_t Bs[TB ? (BN * BK) : (BK * (BN + 8))];

    A += (long long)blockIdx.z * sA;
    B += (long long)blockIdx.z * sB;
    C += (long long)blockIdx.z * sC;

    const int tid  = threadIdx.x;
    const int lane = tid & 31;
    const int wid  = tid >> 5;
    const int warp_m = wid >> 2;   // 0..1 -> 64-row slab
    const int warp_n = wid & 3;    // 0..3 -> 32-col slab
    const int g   = lane >> 2;     // 0..7
    const int tig = lane & 3;      // 0..3

    const int row0 = blockIdx.y * BM;
    const int col0 = blockIdx.x * BN;

    // Loader coords: 4 float4 per thread per operand tile.
    int a_r[4], a_c[4], b_r[4], b_c[4];
#pragma unroll
    for (int i = 0; i < 4; i++) {
        int idx = tid + i * 256;
        a_r[i] = idx >> 3;            // 0..127  (m)
        a_c[i] = (idx & 7) * 4;       // 0..28   (k words)
        if (TB) { b_r[i] = idx >> 3;  b_c[i] = (idx & 7) * 4; }   // n, k
        else    { b_r[i] = idx >> 5;  b_c[i] = (idx & 31) * 4; }  // k, n
    }

    float4 ra[4], rb[4];
    float acc[4][4][4];
#pragma unroll
    for (int mt = 0; mt < 4; mt++)
#pragma unroll
        for (int nt = 0; nt < 4; nt++)
#pragma unroll
            for (int i = 0; i < 4; i++) acc[mt][nt][i] = 0.0f;

    auto LOAD = [&](int k0) {
#pragma unroll
        for (int i = 0; i < 4; i++)
            ra[i] = *(const float4*)&A[(long long)(row0 + a_r[i]) * lda + k0 + a_c[i]];
#pragma unroll
        for (int i = 0; i < 4; i++) {
            if (TB)
                rb[i] = *(const float4*)&B[(long long)(col0 + b_r[i]) * ldb + k0 + b_c[i]];
            else
                rb[i] = *(const float4*)&B[(long long)(k0 + b_r[i]) * ldb + col0 + b_c[i]];
        }
    };

    auto STORE = [&]() {
#pragma unroll
        for (int i = 0; i < 4; i++) {
            uint4 u;
            u.x = f2tf32(ra[i].x); u.y = f2tf32(ra[i].y);
            u.z = f2tf32(ra[i].z); u.w = f2tf32(ra[i].w);
            *(uint4*)&As[swz(a_r[i], a_c[i])] = u;
        }
#pragma unroll
        for (int i = 0; i < 4; i++) {
            uint4 u;
            u.x = f2tf32(rb[i].x); u.y = f2tf32(rb[i].y);
            u.z = f2tf32(rb[i].z); u.w = f2tf32(rb[i].w);
            if (TB)
                *(uint4*)&Bs[swz(b_r[i], b_c[i])] = u;
            else
                *(uint4*)&Bs[b_r[i] * (BN + 8) + b_c[i]] = u;
        }
    };

    auto COMPUTE = [&]() {
#pragma unroll
        for (int ks = 0; ks < 4; ks++) {
            const int kl = ks * 8;
            uint32_t af[4][4];
#pragma unroll
            for (int mt = 0; mt < 4; mt++) {
                const int m = warp_m * 64 + mt * 16;
                af[mt][0] = As[swz(m + g,     kl + tig)];
                af[mt][1] = As[swz(m + g + 8, kl + tig)];
                af[mt][2] = As[swz(m + g,     kl + tig + 4)];
                af[mt][3] = As[swz(m + g + 8, kl + tig + 4)];
            }
#pragma unroll
            for (int nt = 0; nt < 4; nt++) {
                const int nb = warp_n * 32 + nt * 8;
                uint32_t b0, b1;
                if (TB) {
                    b0 = Bs[swz(nb + g, kl + tig)];
                    b1 = Bs[swz(nb + g, kl + tig + 4)];
                } else {
                    b0 = Bs[(kl + tig)     * (BN + 8) + nb + g];
                    b1 = Bs[(kl + tig + 4) * (BN + 8) + nb + g];
                }
#pragma unroll
                for (int mt = 0; mt < 4; mt++) {
                    asm volatile(
                        "mma.sync.aligned.m16n8k8.row.col.f32.tf32.tf32.f32 "
                        "{%0,%1,%2,%3}, {%4,%5,%6,%7}, {%8,%9}, {%0,%1,%2,%3};"
                        : "+f"(acc[mt][nt][0]), "+f"(acc[mt][nt][1]),
                          "+f"(acc[mt][nt][2]), "+f"(acc[mt][nt][3])
                        : "r"(af[mt][0]), "r"(af[mt][1]),
                          "r"(af[mt][2]), "r"(af[mt][3]),
                          "r"(b0), "r"(b1));
                }
            }
        }
    };

    const int nT = K / BK;
    LOAD(0);
    STORE();
    __syncthreads();
    for (int t = 1; t < nT; t++) {
        LOAD(t * BK);       // global prefetch overlaps compute below
        COMPUTE();
        __syncthreads();
        STORE();
        __syncthreads();
    }
    COMPUTE();

    // Epilogue
#pragma unroll
    for (int mt = 0; mt < 4; mt++) {
        const int r = row0 + warp_m * 64 + mt * 16 + g;
#pragma unroll
        for (int nt = 0; nt < 4; nt++) {
            const int c = col0 + warp_n * 32 + nt * 8 + tig * 2;
            float2 v0, v1;
            v0.x = acc[mt][nt][0] * alpha; v0.y = acc[mt][nt][1] * alpha;
            v1.x = acc[mt][nt][2] * alpha; v1.y = acc[mt][nt][3] * alpha;
            *(float2*)&C[(long long)r * ldc + c]       = v0;
            *(float2*)&C[(long long)(r + 8) * ldc + c] = v1;
        }
    }
}

// ---------------------------------------------------------------------------
// Row softmax over n=4096 (one block of 256 threads per row; 16 values/thread)
// ---------------------------------------------------------------------------
__global__ void __launch_bounds__(256)
softmax_kernel(float* __restrict__ s)
{
    __shared__ float red[256];
    const long long row = blockIdx.x;
    float* p = s + row * (long long)SS;
    const int tid = threadIdx.x;

    float v[16];
    float mx = -1e30f;
#pragma unroll
    for (int i = 0; i < 16; i++) {
        v[i] = p[tid + i * 256];
        mx = fmaxf(mx, v[i]);
    }
    red[tid] = mx;
    __syncthreads();
    for (int w = 128; w > 0; w >>= 1) {
        if (tid < w) red[tid] = fmaxf(red[tid], red[tid + w]);
        __syncthreads();
    }
    mx = red[0];
    __syncthreads();

    float sum = 0.0f;
#pragma unroll
    for (int i = 0; i < 16; i++) {
        v[i] = __expf(v[i] - mx);
        sum += v[i];
    }
    red[tid] = sum;
    __syncthreads();
    for (int w = 128; w > 0; w >>= 1) {
        if (tid < w) red[tid] += red[tid + w];
        __syncthreads();
    }
    const float inv = 1.0f / red[0];
#pragma unroll
    for (int i = 0; i < 16; i++)
        p[tid + i * 256] = v[i] * inv;
}

// ---------------------------------------------------------------------------
extern "C" void kernel_launch(void* const* d_in, const int* in_sizes, int n_in,
                              void* d_out, int out_size)
{
    const float* x  = (const float*)d_in[0];
    const float* wq = (const float*)d_in[1];
    const float* wk = (const float*)d_in[2];
    const float* wv = (const float*)d_in[3];
    float* out = (float*)d_out;

    float *q, *k, *v, *s;
    cudaGetSymbolAddress((void**)&q, g_q);
    cudaGetSymbolAddress((void**)&k, g_k);
    cudaGetSymbolAddress((void**)&v, g_v);
    cudaGetSymbolAddress((void**)&s, g_s);

    const long long qkvStride = (long long)SS * DD;  // per-batch Q/K/V
    const long long sStride   = (long long)SS * SS;  // per-batch scores
    const float scale = 1.0f / sqrtf((float)DD);

    dim3 blk(256);

    // 1) QKV projections: [8192,512] x [512,512] (NN)
    {
        dim3 grid(DD / BN, (BB * SS) / BM, 1);
        gemm_tf32<false><<<grid, blk>>>(x, wq, q, DD, DD, DD, DD, 0, 0, 0, 1.0f);
        gemm_tf32<false><<<grid, blk>>>(x, wk, k, DD, DD, DD, DD, 0, 0, 0, 1.0f);
        gemm_tf32<false><<<grid, blk>>>(x, wv, v, DD, DD, DD, DD, 0, 0, 0, 1.0f);
    }

    // 2) scores = scale * Q @ K^T  (NT), per batch
    {
        dim3 grid(SS / BN, SS / BM, BB);
        gemm_tf32<true><<<grid, blk>>>(q, k, s, DD, DD, DD, SS,
                                       qkvStride, qkvStride, sStride, scale);
    }

    // 3) softmax rows
    {
        dim3 grid(BB * SS);
        softmax_kernel<<<grid, blk>>>(s);
    }

    // 4) context = P @ V  (NN), per batch
    {
        dim3 grid(DD / BN, SS / BM, BB);
        gemm_tf32<false><<<grid, blk>>>(s, v, out, SS, SS, DD, DD,
                                        sStride, qkvStride, qkvStride, 1.0f);
    }
}